// round 8
// baseline (speedup 1.0000x reference)
#include <cuda_runtime.h>
#include <cuda_fp16.h>
#include <mma.h>

using namespace nvcuda;

// Problem constants (shapes fixed by the reference).
#define NMAX   100000
#define NEMAX  1600000
#define FEAT   64
#define SCAN_T 256

// ---------------- device scratch (no allocations allowed) ----------------
// g_t padded by 128 rows: last GEMM block stores a full 128-row tile unguarded.
__device__ float    g_t[(NMAX + 128) * FEAT];    // fp32 staging (GEMM output)
__device__ __half   g_t16[(NMAX + 128) * FEAT];  // fp16 features for gather
__device__ float    g_h[NMAX * FEAT];
__device__ unsigned g_degout[NMAX];
__device__ unsigned g_degin[NMAX];
__device__ float    g_iso[NMAX];          // D_out^{-1/2}
__device__ float    g_isi[NMAX];          // D_in^{-1/2}
__device__ int      g_rowstart[NMAX + 1]; // CSR row offsets (by dst)
__device__ int      g_cursor[NMAX];       // fill cursors
__device__ int      g_csr[NEMAX];         // src ids grouped by dst
__device__ int      g_blksum[512];        // scan block totals

// ---------------- degree / normalizer kernels ----------------

__global__ void zero_deg_kernel(int nn) {
    int i = blockIdx.x * blockDim.x + threadIdx.x;
    if (i < nn) { g_degout[i] = 0u; g_degin[i] = 0u; g_cursor[i] = 0; }
    if (i == 0) g_rowstart[0] = 0;
}

__global__ void deg_kernel(const int* __restrict__ src, const int* __restrict__ dst, int ne) {
    int e = blockIdx.x * blockDim.x + threadIdx.x;
    if (e < ne) {
        atomicAdd(&g_degout[src[e]], 1u);
        atomicAdd(&g_degin[dst[e]], 1u);
    }
}

__global__ void inv_kernel(int nn) {
    int i = blockIdx.x * blockDim.x + threadIdx.x;
    if (i < nn) {
        g_iso[i] = rsqrtf(fmaxf((float)g_degout[i], 1.0f));
        g_isi[i] = rsqrtf(fmaxf((float)g_degin[i], 1.0f));
    }
}

// ---------------- prefix-sum (exclusive) over in-degrees -> g_rowstart ----------------
__global__ void scanA_kernel(int nn) {
    __shared__ int sh[SCAN_T];
    int tid = threadIdx.x;
    int i = blockIdx.x * SCAN_T + tid;
    int v = (i < nn) ? (int)g_degin[i] : 0;
    sh[tid] = v;
    __syncthreads();
#pragma unroll
    for (int off = 1; off < SCAN_T; off <<= 1) {
        int t = (tid >= off) ? sh[tid - off] : 0;
        __syncthreads();
        sh[tid] += t;
        __syncthreads();
    }
    if (i < nn) g_rowstart[i + 1] = sh[tid];
    if (tid == SCAN_T - 1) g_blksum[blockIdx.x] = sh[tid];
}

__global__ void scanB_kernel(int nb) {
    __shared__ int sh[512];
    int tid = threadIdx.x;
    sh[tid] = (tid < nb) ? g_blksum[tid] : 0;
    __syncthreads();
#pragma unroll
    for (int off = 1; off < 512; off <<= 1) {
        int t = (tid >= off) ? sh[tid - off] : 0;
        __syncthreads();
        sh[tid] += t;
        __syncthreads();
    }
    g_blksum[tid] = sh[tid];
}

__global__ void scanC_kernel(int nn) {
    int i = blockIdx.x * SCAN_T + threadIdx.x;
    if (i < nn && blockIdx.x > 0) g_rowstart[i + 1] += g_blksum[blockIdx.x - 1];
}

__global__ void csr_fill_kernel(const int* __restrict__ src, const int* __restrict__ dst, int ne) {
    int e = blockIdx.x * blockDim.x + threadIdx.x;
    if (e < ne) {
        int d = dst[e];
        int pos = atomicAdd(&g_cursor[d], 1);
        g_csr[g_rowstart[d] + pos] = src[e];
    }
}

// ---------------- dense transform via TF32 tensor cores ----------------
// T = (X * iso) @ W. Block tile: 128 nodes x 64 cols, 256 threads (8 warps).
// Epilogue converts the block's fp32 tile (L1-hot) to fp16 in g_t16.
template <int K>
__global__ void gemm_mma_kernel(const float* __restrict__ X, const float* __restrict__ W, int nn) {
    constexpr int KC  = 32;
    constexpr int XLD = KC + 4;       // 36 floats; multiple of 4 for wmma ldm
    constexpr int WLD = FEAT + 4;     // 68 floats

    __shared__ float Ws[KC][WLD];     // weight K-chunk
    __shared__ float Xs[128][XLD];    // node-feature K-chunk (iso-scaled)

    const int tid = threadIdx.x;
    const int wid = tid >> 5;
    const int warp_row = wid >> 1;    // 0..3 -> 32-row band
    const int warp_col = wid & 1;     // 0..1 -> 32-col band
    const int nodeBase = blockIdx.x * 128;

    wmma::fragment<wmma::accumulator, 16, 16, 8, float> acc[2][2];
#pragma unroll
    for (int r = 0; r < 2; r++)
#pragma unroll
        for (int c = 0; c < 2; c++) wmma::fill_fragment(acc[r][c], 0.0f);

    for (int k0 = 0; k0 < K; k0 += KC) {
#pragma unroll
        for (int i = tid; i < KC * (FEAT / 4); i += 256) {
            int r = i >> 4, c4 = i & 15;
            float4 v = *reinterpret_cast<const float4*>(&W[(k0 + r) * FEAT + c4 * 4]);
            *reinterpret_cast<float4*>(&Ws[r][c4 * 4]) = v;
        }
#pragma unroll
        for (int i = tid; i < 128 * (KC / 4); i += 256) {
            int r = i / (KC / 4), c4 = i % (KC / 4);
            int node = nodeBase + r;
            float4 v = make_float4(0.f, 0.f, 0.f, 0.f);
            if (node < nn) {
                v = *reinterpret_cast<const float4*>(&X[(size_t)node * K + k0 + c4 * 4]);
                float s = g_iso[node];
                v.x *= s; v.y *= s; v.z *= s; v.w *= s;
            }
            *reinterpret_cast<float4*>(&Xs[r][c4 * 4]) = v;
        }
        __syncthreads();

#pragma unroll
        for (int kk = 0; kk < KC; kk += 8) {
            wmma::fragment<wmma::matrix_a, 16, 16, 8, wmma::precision::tf32, wmma::row_major> a[2];
            wmma::fragment<wmma::matrix_b, 16, 16, 8, wmma::precision::tf32, wmma::row_major> b[2];
#pragma unroll
            for (int r = 0; r < 2; r++) {
                wmma::load_matrix_sync(a[r], &Xs[warp_row * 32 + r * 16][kk], XLD);
#pragma unroll
                for (int t = 0; t < a[r].num_elements; t++)
                    a[r].x[t] = wmma::__float_to_tf32(a[r].x[t]);
            }
#pragma unroll
            for (int c = 0; c < 2; c++) {
                wmma::load_matrix_sync(b[c], &Ws[kk][warp_col * 32 + c * 16], WLD);
#pragma unroll
                for (int t = 0; t < b[c].num_elements; t++)
                    b[c].x[t] = wmma::__float_to_tf32(b[c].x[t]);
            }
#pragma unroll
            for (int r = 0; r < 2; r++)
#pragma unroll
                for (int c = 0; c < 2; c++)
                    wmma::mma_sync(acc[r][c], a[r], b[c], acc[r][c]);
        }
        __syncthreads();
    }

    // Store fp32 tile (padded array -> unguarded stores safe).
#pragma unroll
    for (int r = 0; r < 2; r++)
#pragma unroll
        for (int c = 0; c < 2; c++) {
            int row = nodeBase + warp_row * 32 + r * 16;
            int col = warp_col * 32 + c * 16;
            wmma::store_matrix_sync(&g_t[(size_t)row * FEAT + col], acc[r][c], FEAT,
                                    wmma::mem_row_major);
        }
    __syncthreads();

    // Convert the block's 128x64 tile to fp16 (reads are L1-hot).
#pragma unroll
    for (int i = tid; i < 128 * FEAT / 2; i += 256) {
        int j = i * 2;
        size_t off = (size_t)nodeBase * FEAT + j;
        float2 f = *reinterpret_cast<const float2*>(&g_t[off]);
        *reinterpret_cast<__half2*>(&g_t16[off]) = __floats2half2_rn(f.x, f.y);
    }
}

// ---------------- CSR gather + finalize ----------------
// 8 lanes per node; each lane owns 8 half columns (16 B load per edge).
template <int RELU>
__global__ void gather_kernel(const float* __restrict__ b, float* __restrict__ out, int nn) {
    int idx = blockIdx.x * blockDim.x + threadIdx.x;
    int node = idx >> 3;
    int c = (idx & 7) << 3;           // half-column base (0,8,...,56)
    if (node >= nn) return;

    int rs = g_rowstart[node];
    int re = g_rowstart[node + 1];

    float acc[8];
#pragma unroll
    for (int i = 0; i < 8; i++) acc[i] = 0.f;

#pragma unroll 4
    for (int p = rs; p < re; ++p) {
        int s = __ldg(&g_csr[p]);     // same addr across 8 lanes -> broadcast
        uint4 u = __ldg(reinterpret_cast<const uint4*>(&g_t16[(size_t)s * FEAT + c]));
        float2 f0 = __half22float2(*reinterpret_cast<__half2*>(&u.x));
        float2 f1 = __half22float2(*reinterpret_cast<__half2*>(&u.y));
        float2 f2 = __half22float2(*reinterpret_cast<__half2*>(&u.z));
        float2 f3 = __half22float2(*reinterpret_cast<__half2*>(&u.w));
        acc[0] += f0.x; acc[1] += f0.y;
        acc[2] += f1.x; acc[3] += f1.y;
        acc[4] += f2.x; acc[5] += f2.y;
        acc[6] += f3.x; acc[7] += f3.y;
    }

    float sN = g_isi[node];
    float4 b0 = *reinterpret_cast<const float4*>(&b[c]);
    float4 b1 = *reinterpret_cast<const float4*>(&b[c + 4]);
    float o[8];
    o[0] = acc[0] * sN + b0.x; o[1] = acc[1] * sN + b0.y;
    o[2] = acc[2] * sN + b0.z; o[3] = acc[3] * sN + b0.w;
    o[4] = acc[4] * sN + b1.x; o[5] = acc[5] * sN + b1.y;
    o[6] = acc[6] * sN + b1.z; o[7] = acc[7] * sN + b1.w;
    if (RELU) {
#pragma unroll
        for (int i = 0; i < 8; i++) o[i] = fmaxf(o[i], 0.f);
    }
    float* dst = &out[(size_t)node * FEAT + c];
    *reinterpret_cast<float4*>(dst)     = make_float4(o[0], o[1], o[2], o[3]);
    *reinterpret_cast<float4*>(dst + 4) = make_float4(o[4], o[5], o[6], o[7]);
}

// ---------------- launch ----------------
extern "C" void kernel_launch(void* const* d_in, const int* in_sizes, int n_in,
                              void* d_out, int out_size) {
    const float* x   = (const float*)d_in[0];
    const int*   src = (const int*)d_in[1];
    const int*   dst = (const int*)d_in[2];
    const float* W1  = (const float*)d_in[3];
    const float* b1  = (const float*)d_in[4];
    const float* W2  = (const float*)d_in[5];
    const float* b2  = (const float*)d_in[6];
    const float* W3  = (const float*)d_in[7];
    const float* b3  = (const float*)d_in[8];
    float* out = (float*)d_out;

    const int nn = in_sizes[0] / 128;   // 100000
    const int ne = in_sizes[1];         // 1600000

    static float* h_ptr = nullptr;
    if (h_ptr == nullptr) {
        cudaGetSymbolAddress((void**)&h_ptr, g_h);
    }

    const int T = 256;
    const int nodeBlk = (nn + T - 1) / T;
    const int edgeBlk = (ne + T - 1) / T;
    const int gathBlk = (nn * 8 + T - 1) / T;
    const int gemmBlk = (nn + 127) / 128;
    const int scanNB  = (nn + SCAN_T - 1) / SCAN_T;

    // ---- one-time graph preprocessing: degrees, normalizers, dst-CSR ----
    zero_deg_kernel<<<nodeBlk, T>>>(nn);
    deg_kernel<<<edgeBlk, T>>>(src, dst, ne);
    inv_kernel<<<nodeBlk, T>>>(nn);
    scanA_kernel<<<scanNB, SCAN_T>>>(nn);
    scanB_kernel<<<1, 512>>>(scanNB);
    scanC_kernel<<<scanNB, SCAN_T>>>(nn);
    csr_fill_kernel<<<edgeBlk, T>>>(src, dst, ne);

    // ---- layer 1: x(128) -> h(64), relu ----
    gemm_mma_kernel<128><<<gemmBlk, 256>>>(x, W1, nn);
    gather_kernel<1><<<gathBlk, T>>>(b1, h_ptr, nn);

    // ---- layer 2: h(64) -> h(64), relu ----
    gemm_mma_kernel<64><<<gemmBlk, 256>>>(h_ptr, W2, nn);
    gather_kernel<1><<<gathBlk, T>>>(b2, h_ptr, nn);

    // ---- layer 3: h(64) -> out(64), no relu ----
    gemm_mma_kernel<64><<<gemmBlk, 256>>>(h_ptr, W3, nn);
    gather_kernel<0><<<gathBlk, T>>>(b3, out, nn);
}

// round 9
// speedup vs baseline: 1.1779x; 1.1779x over previous
#include <cuda_runtime.h>
#include <cuda_fp16.h>
#include <mma.h>

using namespace nvcuda;

// Problem constants (shapes fixed by the reference).
#define NMAX   100000
#define NEMAX  1600000
#define FEAT   64
#define SCAN_T 256

// ---------------- device scratch (no allocations allowed) ----------------
// g_t16 padded by 128 rows: last GEMM block stores a full 128-row tile unguarded.
__device__ __half   g_t16[(NMAX + 128) * FEAT];  // fp16 features for gather
__device__ float    g_h[NMAX * FEAT];
__device__ unsigned g_degout[NMAX];
__device__ unsigned g_degin[NMAX];
__device__ float    g_iso[NMAX];          // D_out^{-1/2}
__device__ float    g_isi[NMAX];          // D_in^{-1/2}
__device__ int      g_rowstart[NMAX + 1]; // CSR row offsets (by dst)
__device__ int      g_cursor[NMAX];       // fill cursors
__device__ int      g_csr[NEMAX];         // src ids grouped by dst
__device__ int      g_blksum[512];        // scan block totals

// ---------------- degree / normalizer kernels ----------------

__global__ void zero_deg_kernel(int nn) {
    int i = blockIdx.x * blockDim.x + threadIdx.x;
    if (i < nn) { g_degout[i] = 0u; g_degin[i] = 0u; g_cursor[i] = 0; }
    if (i == 0) g_rowstart[0] = 0;
}

__global__ void deg_kernel(const int* __restrict__ src, const int* __restrict__ dst, int ne) {
    int e = blockIdx.x * blockDim.x + threadIdx.x;
    if (e < ne) {
        atomicAdd(&g_degout[src[e]], 1u);
        atomicAdd(&g_degin[dst[e]], 1u);
    }
}

__global__ void inv_kernel(int nn) {
    int i = blockIdx.x * blockDim.x + threadIdx.x;
    if (i < nn) {
        g_iso[i] = rsqrtf(fmaxf((float)g_degout[i], 1.0f));
        g_isi[i] = rsqrtf(fmaxf((float)g_degin[i], 1.0f));
    }
}

// ---------------- prefix-sum (exclusive) over in-degrees -> g_rowstart ----------------
__global__ void scanA_kernel(int nn) {
    __shared__ int sh[SCAN_T];
    int tid = threadIdx.x;
    int i = blockIdx.x * SCAN_T + tid;
    int v = (i < nn) ? (int)g_degin[i] : 0;
    sh[tid] = v;
    __syncthreads();
#pragma unroll
    for (int off = 1; off < SCAN_T; off <<= 1) {
        int t = (tid >= off) ? sh[tid - off] : 0;
        __syncthreads();
        sh[tid] += t;
        __syncthreads();
    }
    if (i < nn) g_rowstart[i + 1] = sh[tid];
    if (tid == SCAN_T - 1) g_blksum[blockIdx.x] = sh[tid];
}

__global__ void scanB_kernel(int nb) {
    __shared__ int sh[512];
    int tid = threadIdx.x;
    sh[tid] = (tid < nb) ? g_blksum[tid] : 0;
    __syncthreads();
#pragma unroll
    for (int off = 1; off < 512; off <<= 1) {
        int t = (tid >= off) ? sh[tid - off] : 0;
        __syncthreads();
        sh[tid] += t;
        __syncthreads();
    }
    g_blksum[tid] = sh[tid];
}

__global__ void scanC_kernel(int nn) {
    int i = blockIdx.x * SCAN_T + threadIdx.x;
    if (i < nn && blockIdx.x > 0) g_rowstart[i + 1] += g_blksum[blockIdx.x - 1];
}

__global__ void csr_fill_kernel(const int* __restrict__ src, const int* __restrict__ dst, int ne) {
    int e = blockIdx.x * blockDim.x + threadIdx.x;
    if (e < ne) {
        int d = dst[e];
        int pos = atomicAdd(&g_cursor[d], 1);
        g_csr[g_rowstart[d] + pos] = src[e];
    }
}

// ---------------- dense transform via TF32 tensor cores ----------------
// T = (X * iso) @ W -> fp16 g_t16 directly (fp32 staged only through smem).
// Block tile: 128 nodes x 64 cols, 256 threads (8 warps).
template <int K>
__global__ void gemm_mma_kernel(const float* __restrict__ X, const float* __restrict__ W, int nn) {
    constexpr int KC  = 32;
    constexpr int XLD = KC + 4;       // 36 floats
    constexpr int WLD = FEAT + 4;     // 68 floats
    constexpr int SLD = FEAT + 4;     // stage leading dim (mult of 4 for wmma)

    // Union: mainloop tiles (27.1 KB) vs fp32 stage tile (34.8 KB).
    __shared__ __align__(16) char smem_raw[128 * SLD * sizeof(float)];
    float (*Ws)[WLD] = reinterpret_cast<float (*)[WLD]>(smem_raw);
    float (*Xs)[XLD] = reinterpret_cast<float (*)[XLD]>(smem_raw + KC * WLD * sizeof(float));
    float (*St)[SLD] = reinterpret_cast<float (*)[SLD]>(smem_raw);

    const int tid = threadIdx.x;
    const int wid = tid >> 5;
    const int warp_row = wid >> 1;    // 0..3 -> 32-row band
    const int warp_col = wid & 1;     // 0..1 -> 32-col band
    const int nodeBase = blockIdx.x * 128;

    wmma::fragment<wmma::accumulator, 16, 16, 8, float> acc[2][2];
#pragma unroll
    for (int r = 0; r < 2; r++)
#pragma unroll
        for (int c = 0; c < 2; c++) wmma::fill_fragment(acc[r][c], 0.0f);

    for (int k0 = 0; k0 < K; k0 += KC) {
#pragma unroll
        for (int i = tid; i < KC * (FEAT / 4); i += 256) {
            int r = i >> 4, c4 = i & 15;
            float4 v = *reinterpret_cast<const float4*>(&W[(k0 + r) * FEAT + c4 * 4]);
            *reinterpret_cast<float4*>(&Ws[r][c4 * 4]) = v;
        }
#pragma unroll
        for (int i = tid; i < 128 * (KC / 4); i += 256) {
            int r = i / (KC / 4), c4 = i % (KC / 4);
            int node = nodeBase + r;
            float4 v = make_float4(0.f, 0.f, 0.f, 0.f);
            if (node < nn) {
                v = *reinterpret_cast<const float4*>(&X[(size_t)node * K + k0 + c4 * 4]);
                float s = g_iso[node];
                v.x *= s; v.y *= s; v.z *= s; v.w *= s;
            }
            *reinterpret_cast<float4*>(&Xs[r][c4 * 4]) = v;
        }
        __syncthreads();

#pragma unroll
        for (int kk = 0; kk < KC; kk += 8) {
            wmma::fragment<wmma::matrix_a, 16, 16, 8, wmma::precision::tf32, wmma::row_major> a[2];
            wmma::fragment<wmma::matrix_b, 16, 16, 8, wmma::precision::tf32, wmma::row_major> b[2];
#pragma unroll
            for (int r = 0; r < 2; r++) {
                wmma::load_matrix_sync(a[r], &Xs[warp_row * 32 + r * 16][kk], XLD);
#pragma unroll
                for (int t = 0; t < a[r].num_elements; t++)
                    a[r].x[t] = wmma::__float_to_tf32(a[r].x[t]);
            }
#pragma unroll
            for (int c = 0; c < 2; c++) {
                wmma::load_matrix_sync(b[c], &Ws[kk][warp_col * 32 + c * 16], WLD);
#pragma unroll
                for (int t = 0; t < b[c].num_elements; t++)
                    b[c].x[t] = wmma::__float_to_tf32(b[c].x[t]);
            }
#pragma unroll
            for (int r = 0; r < 2; r++)
#pragma unroll
                for (int c = 0; c < 2; c++)
                    wmma::mma_sync(acc[r][c], a[r], b[c], acc[r][c]);
        }
        __syncthreads();
    }

    // Epilogue: fp32 tile -> smem stage -> packed fp16 global stores.
#pragma unroll
    for (int r = 0; r < 2; r++)
#pragma unroll
        for (int c = 0; c < 2; c++)
            wmma::store_matrix_sync(&St[warp_row * 32 + r * 16][warp_col * 32 + c * 16],
                                    acc[r][c], SLD, wmma::mem_row_major);
    __syncthreads();

    // 128x64 floats -> 8 halves (uint4) per thread-item; rows padded so OOB safe.
#pragma unroll
    for (int i = tid; i < 128 * (FEAT / 8); i += 256) {
        int r = i >> 3;
        int c8 = (i & 7) * 8;
        float4 f0 = *reinterpret_cast<float4*>(&St[r][c8]);
        float4 f1 = *reinterpret_cast<float4*>(&St[r][c8 + 4]);
        __half2 h0 = __floats2half2_rn(f0.x, f0.y);
        __half2 h1 = __floats2half2_rn(f0.z, f0.w);
        __half2 h2 = __floats2half2_rn(f1.x, f1.y);
        __half2 h3 = __floats2half2_rn(f1.z, f1.w);
        uint4 pack;
        pack.x = *reinterpret_cast<unsigned*>(&h0);
        pack.y = *reinterpret_cast<unsigned*>(&h1);
        pack.z = *reinterpret_cast<unsigned*>(&h2);
        pack.w = *reinterpret_cast<unsigned*>(&h3);
        *reinterpret_cast<uint4*>(&g_t16[(size_t)(nodeBase + r) * FEAT + c8]) = pack;
    }
}

// ---------------- CSR gather + finalize ----------------
// 16 lanes per node; each lane owns 4 half columns (8 B load per edge).
template <int RELU>
__global__ void gather_kernel(const float* __restrict__ b, float* __restrict__ out, int nn) {
    int idx = blockIdx.x * blockDim.x + threadIdx.x;
    int node = idx >> 4;
    int c = (idx & 15) << 2;          // half-column base (0,4,...,60)
    if (node >= nn) return;

    int rs = g_rowstart[node];
    int re = g_rowstart[node + 1];

    float acc0 = 0.f, acc1 = 0.f, acc2 = 0.f, acc3 = 0.f;

#pragma unroll 4
    for (int p = rs; p < re; ++p) {
        int s = __ldg(&g_csr[p]);     // same addr across 16 lanes -> broadcast
        uint2 u = __ldg(reinterpret_cast<const uint2*>(&g_t16[(size_t)s * FEAT + c]));
        float2 f0 = __half22float2(*reinterpret_cast<__half2*>(&u.x));
        float2 f1 = __half22float2(*reinterpret_cast<__half2*>(&u.y));
        acc0 += f0.x; acc1 += f0.y; acc2 += f1.x; acc3 += f1.y;
    }

    float sN = g_isi[node];
    float4 bb = *reinterpret_cast<const float4*>(&b[c]);
    float4 o;
    o.x = acc0 * sN + bb.x;
    o.y = acc1 * sN + bb.y;
    o.z = acc2 * sN + bb.z;
    o.w = acc3 * sN + bb.w;
    if (RELU) {
        o.x = fmaxf(o.x, 0.f); o.y = fmaxf(o.y, 0.f);
        o.z = fmaxf(o.z, 0.f); o.w = fmaxf(o.w, 0.f);
    }
    *reinterpret_cast<float4*>(&out[(size_t)node * FEAT + c]) = o;
}

// ---------------- launch ----------------
extern "C" void kernel_launch(void* const* d_in, const int* in_sizes, int n_in,
                              void* d_out, int out_size) {
    const float* x   = (const float*)d_in[0];
    const int*   src = (const int*)d_in[1];
    const int*   dst = (const int*)d_in[2];
    const float* W1  = (const float*)d_in[3];
    const float* b1  = (const float*)d_in[4];
    const float* W2  = (const float*)d_in[5];
    const float* b2  = (const float*)d_in[6];
    const float* W3  = (const float*)d_in[7];
    const float* b3  = (const float*)d_in[8];
    float* out = (float*)d_out;

    const int nn = in_sizes[0] / 128;   // 100000
    const int ne = in_sizes[1];         // 1600000

    static float* h_ptr = nullptr;
    if (h_ptr == nullptr) {
        cudaGetSymbolAddress((void**)&h_ptr, g_h);
    }

    const int T = 256;
    const int nodeBlk = (nn + T - 1) / T;
    const int edgeBlk = (ne + T - 1) / T;
    const int gathBlk = (nn * 16 + T - 1) / T;
    const int gemmBlk = (nn + 127) / 128;
    const int scanNB  = (nn + SCAN_T - 1) / SCAN_T;

    // ---- one-time graph preprocessing: degrees, normalizers, dst-CSR ----
    zero_deg_kernel<<<nodeBlk, T>>>(nn);
    deg_kernel<<<edgeBlk, T>>>(src, dst, ne);
    inv_kernel<<<nodeBlk, T>>>(nn);
    scanA_kernel<<<scanNB, SCAN_T>>>(nn);
    scanB_kernel<<<1, 512>>>(scanNB);
    scanC_kernel<<<scanNB, SCAN_T>>>(nn);
    csr_fill_kernel<<<edgeBlk, T>>>(src, dst, ne);

    // ---- layer 1: x(128) -> h(64), relu ----
    gemm_mma_kernel<128><<<gemmBlk, 256>>>(x, W1, nn);
    gather_kernel<1><<<gathBlk, T>>>(b1, h_ptr, nn);

    // ---- layer 2: h(64) -> h(64), relu ----
    gemm_mma_kernel<64><<<gemmBlk, 256>>>(h_ptr, W2, nn);
    gather_kernel<1><<<gathBlk, T>>>(b2, h_ptr, nn);

    // ---- layer 3: h(64) -> out(64), no relu ----
    gemm_mma_kernel<64><<<gemmBlk, 256>>>(h_ptr, W3, nn);
    gather_kernel<0><<<gathBlk, T>>>(b3, out, nn);
}